// round 3
// baseline (speedup 1.0000x reference)
#include <cuda_runtime.h>
#include <cuda_bf16.h>
#include <math.h>
#include <stdint.h>

// ---------------------------------------------------------------------------
// QuantumTSTransformer: 12-qubit statevector sim.
//   B=64 batches, T=32 timesteps, DEGREE=4, sim14 ansatz 2 layers (96 rots),
//   qff readout layer (48 rots), DIM=4096.
// Strategy: one CTA per circuit group; state lives in smem (32KB), gates applied
// in 8 "phases" per layer where 4 qubits are register-resident (16 complex amps
// per thread, 256 threads). XOR swizzle on smem index avoids bank conflicts.
// ---------------------------------------------------------------------------

#define NQ       12
#define DIM      4096
#define BATCH    64
#define TSTEPS   32
#define NROTS    96
#define QFFROTS  48
#define DEGREE   4
#define FDIM     64
#define ODIM     8
#define TGROUP   4                     // t-values per CTA in circuit kernel
#define NBLK_CIRC (BATCH * (TSTEPS / TGROUP))   // 512

// Scratch (device globals: no allocation allowed)
__device__ float2 g_work[DEGREE + 1][BATCH * DIM];   // work_0=base, work_1..4
__device__ float2 g_cs[BATCH * TSTEPS * NROTS];      // (cos(h), sin(h)) per rot
__device__ float2 g_csqff[QFFROTS];

// smem slot swizzle: bijective, conflict-free for all phase patterns
__device__ __forceinline__ uint32_t sw(uint32_t i) { return i ^ ((i >> 4) & 0xFu); }

// base address: deposit 8 tid bits into the amplitude-index bits NOT in {P0..P3}
template<int P0, int P1, int P2, int P3>
__device__ __forceinline__ uint32_t phase_base(int tid) {
    constexpr uint32_t M = (1u << P0) | (1u << P1) | (1u << P2) | (1u << P3);
    uint32_t base = 0;
    int tb = 0;
#pragma unroll
    for (int pos = 0; pos < NQ; ++pos) {
        if (!((M >> pos) & 1u)) {
            base |= ((uint32_t)(tid >> tb) & 1u) << pos;
            ++tb;
        }
    }
    return base;
}

template<int P0, int P1, int P2, int P3>
__device__ __forceinline__ uint32_t pidx(uint32_t base, int j) {
    return base
        | ((j & 1) ? (1u << P0) : 0u)
        | ((j & 2) ? (1u << P1) : 0u)
        | ((j & 4) ? (1u << P2) : 0u)
        | ((j & 8) ? (1u << P3) : 0u);
}

// RY on register-bit RB:  a0' = c a0 - s a1 ; a1' = s a0 + c a1
template<int RB>
__device__ __forceinline__ void gry(float2* r, float2 cs) {
    const float c = cs.x, s = cs.y;
#pragma unroll
    for (int j = 0; j < 16; ++j) {
        if (!(j & (1 << RB))) {
            float2 a0 = r[j], a1 = r[j | (1 << RB)];
            r[j].x = c * a0.x - s * a1.x;
            r[j].y = c * a0.y - s * a1.y;
            r[j | (1 << RB)].x = s * a0.x + c * a1.x;
            r[j | (1 << RB)].y = s * a0.y + c * a1.y;
        }
    }
}

// CRX: control register-bit RBC == 1, target RBT.
//   a0' = c a0 - i s a1 ; a1' = c a1 - i s a0
template<int RBC, int RBT>
__device__ __forceinline__ void gcrx(float2* r, float2 cs) {
    const float c = cs.x, s = cs.y;
#pragma unroll
    for (int j = 0; j < 16; ++j) {
        if ((j & (1 << RBC)) && !(j & (1 << RBT))) {
            float2 a0 = r[j], a1 = r[j | (1 << RBT)];
            r[j].x = c * a0.x + s * a1.y;
            r[j].y = c * a0.y - s * a1.x;
            r[j | (1 << RBT)].x = c * a1.x + s * a0.y;
            r[j | (1 << RBT)].y = c * a1.y - s * a0.x;
        }
    }
}

#define PHASE_LOAD(P0,P1,P2,P3)                                            \
    uint32_t base = phase_base<P0,P1,P2,P3>(tid);                          \
    float2 r[16];                                                          \
    _Pragma("unroll")                                                      \
    for (int j = 0; j < 16; ++j) r[j] = st[sw(pidx<P0,P1,P2,P3>(base, j))];

#define PHASE_STORE(P0,P1,P2,P3)                                           \
    _Pragma("unroll")                                                      \
    for (int j = 0; j < 16; ++j) st[sw(pidx<P0,P1,P2,P3>(base, j))] = r[j];

// ---- the 8 phases of one sim14 layer (wire w <-> amplitude bit 11-w) ----
// Layer = RY ring (idx 0..11) fused with chainA (idx 12..23), then RY ring
// (24..35) fused with chainB (36..47). Groupings preserve gate ordering.

__device__ __forceinline__ void phA1(float2* st, const float2* c, int tid) {
    // wires {0,11,10,9} -> bits {11,0,1,2}
    PHASE_LOAD(11, 0, 1, 2);
    gry<0>(r, c[0]);  gry<1>(r, c[11]); gry<2>(r, c[10]); gry<3>(r, c[9]);
    gcrx<1, 0>(r, c[12]);   // CRX(11->0)
    gcrx<2, 1>(r, c[13]);   // CRX(10->11)
    gcrx<3, 2>(r, c[14]);   // CRX(9->10)
    PHASE_STORE(11, 0, 1, 2);
}
__device__ __forceinline__ void phA2(float2* st, const float2* c, int tid) {
    // wires {9,8,7,6} -> bits {2,3,4,5}
    PHASE_LOAD(2, 3, 4, 5);
    gry<1>(r, c[8]); gry<2>(r, c[7]); gry<3>(r, c[6]);
    gcrx<1, 0>(r, c[15]);   // CRX(8->9)
    gcrx<2, 1>(r, c[16]);   // CRX(7->8)
    gcrx<3, 2>(r, c[17]);   // CRX(6->7)
    PHASE_STORE(2, 3, 4, 5);
}
__device__ __forceinline__ void phA3(float2* st, const float2* c, int tid) {
    // wires {6,5,4,3} -> bits {5,6,7,8}
    PHASE_LOAD(5, 6, 7, 8);
    gry<1>(r, c[5]); gry<2>(r, c[4]); gry<3>(r, c[3]);
    gcrx<1, 0>(r, c[18]);   // CRX(5->6)
    gcrx<2, 1>(r, c[19]);   // CRX(4->5)
    gcrx<3, 2>(r, c[20]);   // CRX(3->4)
    PHASE_STORE(5, 6, 7, 8);
}
__device__ __forceinline__ void phA4(float2* st, const float2* c, int tid) {
    // wires {3,2,1,0} -> bits {8,9,10,11}
    PHASE_LOAD(8, 9, 10, 11);
    gry<1>(r, c[2]); gry<2>(r, c[1]);
    gcrx<1, 0>(r, c[21]);   // CRX(2->3)
    gcrx<2, 1>(r, c[22]);   // CRX(1->2)
    gcrx<3, 2>(r, c[23]);   // CRX(0->1)
    PHASE_STORE(8, 9, 10, 11);
}
__device__ __forceinline__ void phB1(float2* st, const float2* c, int tid) {
    // wires {10,11,0,1} -> bits {1,0,11,10}
    PHASE_LOAD(1, 0, 11, 10);
    gry<0>(r, c[34]); gry<1>(r, c[35]); gry<2>(r, c[24]); gry<3>(r, c[25]);
    gcrx<1, 0>(r, c[36]);   // CRX(11->10)
    gcrx<2, 1>(r, c[37]);   // CRX(0->11)
    gcrx<3, 2>(r, c[38]);   // CRX(1->0)
    PHASE_STORE(1, 0, 11, 10);
}
__device__ __forceinline__ void phB2(float2* st, const float2* c, int tid) {
    // wires {1,2,3,4} -> bits {10,9,8,7}
    PHASE_LOAD(10, 9, 8, 7);
    gry<1>(r, c[26]); gry<2>(r, c[27]); gry<3>(r, c[28]);
    gcrx<1, 0>(r, c[39]);   // CRX(2->1)
    gcrx<2, 1>(r, c[40]);   // CRX(3->2)
    gcrx<3, 2>(r, c[41]);   // CRX(4->3)
    PHASE_STORE(10, 9, 8, 7);
}
__device__ __forceinline__ void phB3(float2* st, const float2* c, int tid) {
    // wires {4,5,6,7} -> bits {7,6,5,4}
    PHASE_LOAD(7, 6, 5, 4);
    gry<1>(r, c[29]); gry<2>(r, c[30]); gry<3>(r, c[31]);
    gcrx<1, 0>(r, c[42]);   // CRX(5->4)
    gcrx<2, 1>(r, c[43]);   // CRX(6->5)
    gcrx<3, 2>(r, c[44]);   // CRX(7->6)
    PHASE_STORE(7, 6, 5, 4);
}
__device__ __forceinline__ void phB4(float2* st, const float2* c, int tid) {
    // wires {7,8,9,10} -> bits {4,3,2,1}
    PHASE_LOAD(4, 3, 2, 1);
    gry<1>(r, c[32]); gry<2>(r, c[33]);
    gcrx<1, 0>(r, c[45]);   // CRX(8->7)
    gcrx<2, 1>(r, c[46]);   // CRX(9->8)
    gcrx<3, 2>(r, c[47]);   // CRX(10->9)
    PHASE_STORE(4, 3, 2, 1);
}

__device__ __forceinline__ void run_layer(float2* st, const float2* c, int tid) {
    phA1(st, c, tid); __syncthreads();
    phA2(st, c, tid); __syncthreads();
    phA3(st, c, tid); __syncthreads();
    phA4(st, c, tid); __syncthreads();
    phB1(st, c, tid); __syncthreads();
    phB2(st, c, tid); __syncthreads();
    phB3(st, c, tid); __syncthreads();
    phB4(st, c, tid); __syncthreads();
}

// ---------------------------------------------------------------------------
// Kernel 1: params. theta = sigmoid(x@W^T + b) * 2pi ; store (cos, sin)(theta/2)
// ---------------------------------------------------------------------------
__global__ void param_kernel(const float* __restrict__ x,
                             const float* __restrict__ Wp,
                             const float* __restrict__ bp,
                             const float* __restrict__ qff) {
    __shared__ float xr[FDIM];
    int bt = blockIdx.x;            // 0..2047
    int r = threadIdx.x;            // 0..95
    if (r < FDIM) xr[r] = x[bt * FDIM + r];
    __syncthreads();
    float acc = bp[r];
#pragma unroll
    for (int f = 0; f < FDIM; ++f) acc += xr[f] * Wp[r * FDIM + f];
    float sg = 1.0f / (1.0f + expf(-acc));
    float h = 3.14159265358979323846f * sg;   // theta/2 = pi * sigmoid
    g_cs[bt * NROTS + r] = make_float2(cosf(h), sinf(h));
    if (bt == 0 && r < QFFROTS) {
        float hq = 0.5f * qff[r];
        g_csqff[r] = make_float2(cosf(hq), sinf(hq));
    }
}

// ---------------------------------------------------------------------------
// Kernel 2: zero scratch, set work_0 = |0...0> per batch
// ---------------------------------------------------------------------------
__global__ void init_kernel() {
    uint32_t e = blockIdx.x * blockDim.x + threadIdx.x;   // 0 .. 5*64*4096-1
    float2* flat = &g_work[0][0];
    uint32_t buf = e >> 18;                 // /262144
    uint32_t rem = e & 0x3FFFFu;
    float2 v = make_float2(0.f, 0.f);
    if (buf == 0 && (rem & (DIM - 1)) == 0) v.x = 1.f;
    flat[e] = v;
}

// ---------------------------------------------------------------------------
// Kernel 3: one polynomial degree.
// grid = 512 (b * 8 tgroups), each CTA runs TGROUP circuits and accumulates
// mix[t]*psi in registers, then RED.global into work_out.
// ---------------------------------------------------------------------------
__global__ void __launch_bounds__(256, 2)
circuit_kernel(const float2* __restrict__ win, float2* __restrict__ wout,
               const float* __restrict__ mix_re, const float* __restrict__ mix_im) {
    __shared__ float2 st[DIM];
    const int tid = threadIdx.x;
    const int b = blockIdx.x >> 3;
    const int tg = blockIdx.x & 7;

    float2 A[16];
#pragma unroll
    for (int j = 0; j < 16; ++j) A[j] = make_float2(0.f, 0.f);

    for (int tt = 0; tt < TGROUP; ++tt) {
        const int t = tg * TGROUP + tt;
        __syncthreads();                      // prior iter readers done
#pragma unroll
        for (int k = 0; k < 16; ++k) {
            int i = tid + 256 * k;
            st[sw((uint32_t)i)] = win[b * DIM + i];
        }
        __syncthreads();

        const float2* c0 = &g_cs[(b * TSTEPS + t) * NROTS];
        run_layer(st, c0, tid);               // layer 0 (8 phases)
        const float2* c1 = c0 + 48;
        // layer 1: first 7 phases, last phase kept in registers
        phA1(st, c1, tid); __syncthreads();
        phA2(st, c1, tid); __syncthreads();
        phA3(st, c1, tid); __syncthreads();
        phA4(st, c1, tid); __syncthreads();
        phB1(st, c1, tid); __syncthreads();
        phB2(st, c1, tid); __syncthreads();
        phB3(st, c1, tid); __syncthreads();
        {   // phB4 without store: accumulate mix[t] * psi
            PHASE_LOAD(4, 3, 2, 1);
            gry<1>(r, c1[32]); gry<2>(r, c1[33]);
            gcrx<1, 0>(r, c1[45]);
            gcrx<2, 1>(r, c1[46]);
            gcrx<3, 2>(r, c1[47]);
            const float mr = mix_re[t], mi = mix_im[t];
#pragma unroll
            for (int j = 0; j < 16; ++j) {
                A[j].x += mr * r[j].x - mi * r[j].y;
                A[j].y += mr * r[j].y + mi * r[j].x;
            }
        }
    }
    // flush accumulator (B4 amplitude mapping)
    uint32_t base = phase_base<4, 3, 2, 1>(tid);
#pragma unroll
    for (int j = 0; j < 16; ++j) {
        uint32_t i = pidx<4, 3, 2, 1>(base, j);
        atomicAdd(&wout[b * DIM + i].x, A[j].x);
        atomicAdd(&wout[b * DIM + i].y, A[j].y);
    }
}

// ---------------------------------------------------------------------------
// Kernel 4: assemble acc, normalize, qff layer, Pauli expvals, output linear.
// grid = 64 (one CTA per batch), 256 threads.
// ---------------------------------------------------------------------------
__global__ void final_kernel(const float* __restrict__ poly,
                             const float* __restrict__ W_out,
                             const float* __restrict__ b_out,
                             float* __restrict__ out) {
    __shared__ float2 st[DIM];
    __shared__ float red[37];            // [0..35] expvals, [36] sumsq
    const int tid = threadIdx.x;
    const int b = blockIdx.x;

    float p[DEGREE + 1];
#pragma unroll
    for (int d = 0; d <= DEGREE; ++d) p[d] = poly[d];
    float sabs = 0.f;
#pragma unroll
    for (int d = 0; d <= DEGREE; ++d) sabs += fabsf(p[d]);
    const float inv_s = 1.f / sabs;

    if (tid == 0) red[36] = 0.f;
    float lsq = 0.f;
#pragma unroll
    for (int k = 0; k < 16; ++k) {
        int i = tid + 256 * k;
        float2 v = make_float2(0.f, 0.f);
#pragma unroll
        for (int d = 0; d <= DEGREE; ++d) {
            float2 w = g_work[d][b * DIM + i];
            v.x += p[d] * w.x;
            v.y += p[d] * w.y;
        }
        v.x *= inv_s; v.y *= inv_s;
        st[sw((uint32_t)i)] = v;
        lsq += v.x * v.x + v.y * v.y;
    }
#pragma unroll
    for (int o = 16; o > 0; o >>= 1) lsq += __shfl_xor_sync(0xffffffffu, lsq, o);
    if ((tid & 31) == 0) atomicAdd(&red[36], lsq);
    __syncthreads();

    const float f = 1.f / (sqrtf(red[36]) + 1e-9f);
#pragma unroll
    for (int k = 0; k < 16; ++k) {
        int i = tid + 256 * k;
        uint32_t s_ = sw((uint32_t)i);
        float2 v = st[s_];
        v.x *= f; v.y *= f;
        st[s_] = v;
    }
    __syncthreads();

    run_layer(st, g_csqff, tid);     // qff: one sim14 layer

    if (tid < 36) red[tid] = 0.f;
    __syncthreads();

    float xx[NQ], yy[NQ], zz[NQ];
#pragma unroll
    for (int w = 0; w < NQ; ++w) { xx[w] = 0.f; yy[w] = 0.f; zz[w] = 0.f; }

#pragma unroll
    for (int k = 0; k < 16; ++k) {
        int i = tid + 256 * k;
        float2 a = st[sw((uint32_t)i)];
        float n2 = a.x * a.x + a.y * a.y;
#pragma unroll
        for (int w = 0; w < NQ; ++w) {
            int pbit = 11 - w;
            if (((i >> pbit) & 1) == 0) {
                float2 a1 = st[sw((uint32_t)(i | (1 << pbit)))];
                xx[w] += 2.f * (a.x * a1.x + a.y * a1.y);
                yy[w] += 2.f * (a.x * a1.y - a.y * a1.x);
                zz[w] += n2;
            } else {
                zz[w] -= n2;
            }
        }
    }
#pragma unroll
    for (int w = 0; w < NQ; ++w) {
        atomicAdd(&red[w], xx[w]);
        atomicAdd(&red[12 + w], yy[w]);
        atomicAdd(&red[24 + w], zz[w]);
    }
    __syncthreads();

    if (tid < ODIM) {
        float acc = b_out[tid];
#pragma unroll
        for (int j = 0; j < 36; ++j) acc += W_out[tid * 36 + j] * red[j];
        out[b * ODIM + tid] = acc;
    }
}

// ---------------------------------------------------------------------------
// Inputs (metadata order): x, W_proj, b_proj, poly_coeffs, mix_re, mix_im,
//                          qff_params, W_out, b_out.  Output: float32 [64,8].
// ---------------------------------------------------------------------------
extern "C" void kernel_launch(void* const* d_in, const int* in_sizes, int n_in,
                              void* d_out, int out_size) {
    (void)in_sizes; (void)n_in; (void)out_size;
    const float* x      = (const float*)d_in[0];
    const float* W_proj = (const float*)d_in[1];
    const float* b_proj = (const float*)d_in[2];
    const float* poly   = (const float*)d_in[3];
    const float* mix_re = (const float*)d_in[4];
    const float* mix_im = (const float*)d_in[5];
    const float* qff    = (const float*)d_in[6];
    const float* W_out  = (const float*)d_in[7];
    const float* b_out  = (const float*)d_in[8];
    float* out = (float*)d_out;

    param_kernel<<<BATCH * TSTEPS, NROTS>>>(x, W_proj, b_proj, qff);
    init_kernel<<<(DEGREE + 1) * BATCH * DIM / 256, 256>>>();

    float2* w0; float2* w1; float2* w2; float2* w3; float2* w4;
    cudaGetSymbolAddress((void**)&w0, g_work);   // base of g_work
    w1 = w0 + 1 * BATCH * DIM;
    w2 = w0 + 2 * BATCH * DIM;
    w3 = w0 + 3 * BATCH * DIM;
    w4 = w0 + 4 * BATCH * DIM;

    circuit_kernel<<<NBLK_CIRC, 256>>>(w0, w1, mix_re, mix_im);
    circuit_kernel<<<NBLK_CIRC, 256>>>(w1, w2, mix_re, mix_im);
    circuit_kernel<<<NBLK_CIRC, 256>>>(w2, w3, mix_re, mix_im);
    circuit_kernel<<<NBLK_CIRC, 256>>>(w3, w4, mix_re, mix_im);

    final_kernel<<<BATCH, 256>>>(poly, W_out, b_out, out);
}